// round 1
// baseline (speedup 1.0000x reference)
#include <cuda_runtime.h>
#include <math.h>

// Shapes are fixed for this problem: N=4096 tokens, C=1024, I=2048, E=8.
#define MAX_N 4096
#define MAX_I 2048
#define MAX_E 8

__device__ float g_inter[(size_t)MAX_N * MAX_I];  // gelu(H @ W1_e), 32 MB scratch
__device__ float g_scale[(size_t)MAX_N * MAX_E];  // act/num_act
__device__ float g_prec[MAX_E + 1];               // inv col norms + logit_scale

#define L2_EPS 1e-12f

__global__ void prec_kernel(const float* __restrict__ sim, const float* __restrict__ temp,
                            int C, int E) {
    int w = threadIdx.x >> 5;
    int lane = threadIdx.x & 31;
    if (w < E) {
        float s = 0.f;
        for (int c = lane; c < C; c += 32) {
            float v = sim[(size_t)c * E + w];
            s += v * v;
        }
        #pragma unroll
        for (int o = 16; o > 0; o >>= 1) s += __shfl_xor_sync(0xffffffffu, s, o);
        if (lane == 0) g_prec[w] = 1.f / fmaxf(sqrtf(s), L2_EPS);
    }
    if (threadIdx.x == 0) g_prec[MAX_E] = 1.f / (1.f + expf(-temp[0]));
}

__global__ void gating_kernel(const float* __restrict__ h, const float* __restrict__ sim,
                              const float* __restrict__ gates, const float* __restrict__ mask,
                              const int* __restrict__ min_experts_p,
                              float* __restrict__ out_logits, float* __restrict__ out_act,
                              int C, int E) {
    const int n = blockIdx.x;
    const int tid = threadIdx.x;
    float hh = 0.f;
    float dot[MAX_E];
    #pragma unroll
    for (int e = 0; e < MAX_E; e++) dot[e] = 0.f;

    const float* hrow = h + (size_t)n * C;
    for (int c = tid; c < C; c += 128) {
        float v = hrow[c];
        hh += v * v;
        const float* srow = sim + (size_t)c * E;
        #pragma unroll
        for (int e = 0; e < MAX_E; e++) {
            if (e < E) dot[e] += v * srow[e];
        }
    }

    __shared__ float sd[(MAX_E + 1) * 128];
    sd[tid] = hh;
    #pragma unroll
    for (int e = 0; e < MAX_E; e++) {
        if (e < E) sd[(e + 1) * 128 + tid] = dot[e];
    }
    __syncthreads();
    for (int s = 64; s > 0; s >>= 1) {
        if (tid < s) {
            for (int r = 0; r <= E; r++)
                sd[r * 128 + tid] += sd[r * 128 + tid + s];
        }
        __syncthreads();
    }

    if (tid == 0) {
        float inv_h = 1.f / fmaxf(sqrtf(sd[0]), L2_EPS);
        float ls = g_prec[MAX_E];
        float logits[MAX_E], act[MAX_E];
        float suma = 0.f;
        for (int e = 0; e < E; e++) {
            float lg = sd[(e + 1) * 128] * inv_h * g_prec[e];
            lg *= mask[e];
            logits[e] = lg;
            float gated = lg - gates[e] * ls;     // relu(.) > 0  <=>  (.) > 0
            float a = (gated > 0.f) ? 1.f : 0.f;
            act[e] = a;
            suma += a;
        }
        if (suma == 0.f) {
            int k = min_experts_p ? *min_experts_p : 2;
            if (k <= 0 || k > E) {
                float f = __int_as_float(k);      // hedge against float-encoded scalar
                int k2 = (int)f;
                k = (k2 > 0 && k2 <= E) ? k2 : 2;
            }
            bool chosen[MAX_E];
            for (int e = 0; e < E; e++) chosen[e] = false;
            for (int j = 0; j < k; j++) {
                int best = -1;
                float bv = -1e30f;
                for (int e = 0; e < E; e++)
                    if (!chosen[e] && logits[e] > bv) { bv = logits[e]; best = e; }
                if (best >= 0) { chosen[best] = true; act[best] = 1.f; suma += 1.f; }
            }
        }
        float num = fmaxf(suma, 1.f);
        for (int e = 0; e < E; e++) {
            out_logits[(size_t)n * E + e] = logits[e];
            out_act[(size_t)n * E + e] = act[e];
            g_scale[(size_t)n * E + e] = act[e] / num;
        }
    }
}

// 128x128x8 fp32 GEMM, 256 threads, 8x8 microtiles.
// MODE 0: g_inter = gelu(A @ B)                  A = hidden [M,K], B = w1_e [K,N]
// MODE 1: Cout   += g_scale[m,e] * (g_inter @ B) B = w2_e [K,N]
template <int MODE>
__global__ __launch_bounds__(256, 2)
void sgemm_kernel(const float* __restrict__ A_in, const float* __restrict__ B,
                  float* __restrict__ Cout, int M, int N, int K, int expert, int E) {
    const int BK = 8;
    __shared__ float As[BK][128];
    __shared__ float Bs[BK][128];

    const float* A = (MODE == 1) ? g_inter : A_in;

    const int tid = threadIdx.x;
    const int bm = blockIdx.y * 128;
    const int bn = blockIdx.x * 128;
    const int tx = tid & 15;
    const int ty = tid >> 4;

    const int arow = tid >> 1;
    const int acol = (tid & 1) * 4;
    const int brow = tid >> 5;
    const int bcol = (tid & 31) * 4;

    float acc[8][8];
    #pragma unroll
    for (int i = 0; i < 8; i++)
        #pragma unroll
        for (int j = 0; j < 8; j++) acc[i][j] = 0.f;

    const float* Ag = A + (size_t)(bm + arow) * K + acol;
    const float* Bg = B + (size_t)brow * N + bn + bcol;

    for (int k0 = 0; k0 < K; k0 += BK) {
        float4 a4 = *(const float4*)(Ag + k0);
        As[acol + 0][arow] = a4.x;
        As[acol + 1][arow] = a4.y;
        As[acol + 2][arow] = a4.z;
        As[acol + 3][arow] = a4.w;
        *(float4*)(&Bs[brow][bcol]) = *(const float4*)(Bg + (size_t)k0 * N);
        __syncthreads();

        #pragma unroll
        for (int kk = 0; kk < BK; kk++) {
            float a[8], b[8];
            float4 av0 = *(const float4*)(&As[kk][ty * 8]);
            float4 av1 = *(const float4*)(&As[kk][ty * 8 + 4]);
            a[0]=av0.x; a[1]=av0.y; a[2]=av0.z; a[3]=av0.w;
            a[4]=av1.x; a[5]=av1.y; a[6]=av1.z; a[7]=av1.w;
            float4 bv0 = *(const float4*)(&Bs[kk][tx * 8]);
            float4 bv1 = *(const float4*)(&Bs[kk][tx * 8 + 4]);
            b[0]=bv0.x; b[1]=bv0.y; b[2]=bv0.z; b[3]=bv0.w;
            b[4]=bv1.x; b[5]=bv1.y; b[6]=bv1.z; b[7]=bv1.w;
            #pragma unroll
            for (int i = 0; i < 8; i++)
                #pragma unroll
                for (int j = 0; j < 8; j++)
                    acc[i][j] = fmaf(a[i], b[j], acc[i][j]);
        }
        __syncthreads();
    }

    #pragma unroll
    for (int i = 0; i < 8; i++) {
        int row = bm + ty * 8 + i;
        if (MODE == 0) {
            #pragma unroll
            for (int j = 0; j < 8; j++) {
                int col = bn + tx * 8 + j;
                float x = acc[i][j];
                g_inter[(size_t)row * N + col] =
                    0.5f * x * (1.f + erff(x * 0.70710678118654752f));
            }
        } else {
            float s = g_scale[(size_t)row * E + expert];
            #pragma unroll
            for (int j = 0; j < 8; j++) {
                int col = bn + tx * 8 + j;
                Cout[(size_t)row * N + col] += s * acc[i][j];
            }
        }
    }
}

extern "C" void kernel_launch(void* const* d_in, const int* in_sizes, int n_in,
                              void* d_out, int out_size) {
    const float* h     = (const float*)d_in[0];
    const float* sim   = (const float*)d_in[1];
    const float* gates = (const float*)d_in[2];
    const float* temp  = (const float*)d_in[3];
    const float* mask  = (const float*)d_in[4];
    const float* w1    = (const float*)d_in[5];
    const float* w2    = (const float*)d_in[6];
    const int*   mi    = (const int*)d_in[7];

    const int E = in_sizes[2];
    const int C = in_sizes[1] / E;
    const int I = in_sizes[5] / (E * C);
    const int N = in_sizes[0] / C;

    float* out_final  = (float*)d_out;
    float* out_logits = out_final + (size_t)N * C;
    float* out_act    = out_logits + (size_t)N * E;

    cudaMemsetAsync(out_final, 0, (size_t)N * C * sizeof(float));
    prec_kernel<<<1, 256>>>(sim, temp, C, E);
    gating_kernel<<<N, 128>>>(h, sim, gates, mask, mi, out_logits, out_act, C, E);

    dim3 g1(I / 128, N / 128);
    dim3 g2(C / 128, N / 128);
    for (int e = 0; e < E; e++) {
        sgemm_kernel<0><<<g1, 256>>>(h, w1 + (size_t)e * C * I, nullptr, N, I, C, e, E);
        sgemm_kernel<1><<<g2, 256>>>(nullptr, w2 + (size_t)e * I * C, out_final, N, C, I, e, E);
    }
}

// round 3
// speedup vs baseline: 2.7491x; 2.7491x over previous
#include <cuda_runtime.h>
#include <cuda_bf16.h>
#include <math.h>
#include <stdint.h>

// Fixed shapes: N=4096 tokens, C=1024, I=2048, E=8.
#define MAX_N 4096
#define MAX_C 1024
#define MAX_I 2048
#define MAX_E 8

// ---------------- device scratch ----------------
__device__ __align__(256) __nv_bfloat16 g_h_hi[(size_t)MAX_N * MAX_C];
__device__ __align__(256) __nv_bfloat16 g_h_lo[(size_t)MAX_N * MAX_C];
__device__ __align__(256) __nv_bfloat16 g_inter_hi[(size_t)MAX_E * MAX_N * MAX_I];
__device__ __align__(256) __nv_bfloat16 g_inter_lo[(size_t)MAX_E * MAX_N * MAX_I];
__device__ __align__(256) __nv_bfloat16 g_w1t_hi[(size_t)MAX_E * MAX_I * MAX_C]; // [E][I][C]
__device__ __align__(256) __nv_bfloat16 g_w1t_lo[(size_t)MAX_E * MAX_I * MAX_C];
__device__ __align__(256) __nv_bfloat16 g_w2t_hi[(size_t)MAX_E * MAX_C * MAX_I]; // [E][C][I]
__device__ __align__(256) __nv_bfloat16 g_w2t_lo[(size_t)MAX_E * MAX_C * MAX_I];
__device__ __align__(256) float g_part[(size_t)MAX_E * MAX_N * MAX_C];
__device__ __align__(256) float g_scale[(size_t)MAX_N * MAX_E];
__device__ float g_prec[MAX_E + 1];

#define L2_EPS 1e-12f

// ---------------- PTX helpers (baseline sm_80+ features only) ----------------
__device__ __forceinline__ uint32_t smem_to_u32(const void* p) {
    uint32_t a;
    asm("{ .reg .u64 t; cvta.to.shared.u64 t, %1; cvt.u32.u64 %0, t; }" : "=r"(a) : "l"(p));
    return a;
}
#define CP_ASYNC16(s, g) \
    asm volatile("cp.async.cg.shared.global [%0], [%1], 16;" :: "r"(s), "l"(g))
#define CP_COMMIT() asm volatile("cp.async.commit_group;" ::: "memory")
#define CP_WAIT0()  asm volatile("cp.async.wait_group 0;" ::: "memory")
#define CP_WAIT1()  asm volatile("cp.async.wait_group 1;" ::: "memory")
#define LDSM4(R, addr) \
    asm volatile("ldmatrix.sync.aligned.m8n8.x4.shared.b16 {%0,%1,%2,%3}, [%4];" \
        : "=r"((R)[0]), "=r"((R)[1]), "=r"((R)[2]), "=r"((R)[3]) : "r"(addr))
#define LDSM2(R, addr) \
    asm volatile("ldmatrix.sync.aligned.m8n8.x2.shared.b16 {%0,%1}, [%2];" \
        : "=r"((R)[0]), "=r"((R)[1]) : "r"(addr))
#define MMA16816(Cc, A, B) \
    asm volatile("mma.sync.aligned.m16n8k16.row.col.f32.bf16.bf16.f32 " \
        "{%0,%1,%2,%3}, {%4,%5,%6,%7}, {%8,%9}, {%0,%1,%2,%3};" \
        : "+f"((Cc)[0]), "+f"((Cc)[1]), "+f"((Cc)[2]), "+f"((Cc)[3]) \
        : "r"((A)[0]), "r"((A)[1]), "r"((A)[2]), "r"((A)[3]), "r"((B)[0]), "r"((B)[1]))

// ---------------- prep: sim col norms + logit scale ----------------
__global__ void prec_kernel(const float* __restrict__ sim, const float* __restrict__ temp,
                            int C, int E) {
    int w = threadIdx.x >> 5, lane = threadIdx.x & 31;
    if (w < E) {
        float s = 0.f;
        for (int c = lane; c < C; c += 32) { float v = sim[(size_t)c * E + w]; s += v * v; }
        #pragma unroll
        for (int o = 16; o > 0; o >>= 1) s += __shfl_xor_sync(0xffffffffu, s, o);
        if (lane == 0) g_prec[w] = 1.f / fmaxf(sqrtf(s), L2_EPS);
    }
    if (threadIdx.x == 0) g_prec[MAX_E] = 1.f / (1.f + expf(-temp[0]));
}

// ---------------- gating ----------------
__global__ void gating_kernel(const float* __restrict__ h, const float* __restrict__ sim,
                              const float* __restrict__ gates, const float* __restrict__ mask,
                              const int* __restrict__ min_experts_p,
                              float* __restrict__ out_logits, float* __restrict__ out_act,
                              int C, int E) {
    const int n = blockIdx.x, tid = threadIdx.x;
    float hh = 0.f;
    float dot[MAX_E];
    #pragma unroll
    for (int e = 0; e < MAX_E; e++) dot[e] = 0.f;
    const float* hrow = h + (size_t)n * C;
    for (int c = tid; c < C; c += 128) {
        float v = hrow[c];
        hh += v * v;
        const float* srow = sim + (size_t)c * E;
        #pragma unroll
        for (int e = 0; e < MAX_E; e++) if (e < E) dot[e] += v * srow[e];
    }
    __shared__ float sd[(MAX_E + 1) * 128];
    sd[tid] = hh;
    #pragma unroll
    for (int e = 0; e < MAX_E; e++) if (e < E) sd[(e + 1) * 128 + tid] = dot[e];
    __syncthreads();
    for (int s = 64; s > 0; s >>= 1) {
        if (tid < s)
            for (int r = 0; r <= E; r++) sd[r * 128 + tid] += sd[r * 128 + tid + s];
        __syncthreads();
    }
    if (tid == 0) {
        float inv_h = 1.f / fmaxf(sqrtf(sd[0]), L2_EPS);
        float ls = g_prec[MAX_E];
        float logits[MAX_E], act[MAX_E];
        float suma = 0.f;
        for (int e = 0; e < E; e++) {
            float lg = sd[(e + 1) * 128] * inv_h * g_prec[e];
            lg *= mask[e];
            logits[e] = lg;
            float gated = lg - gates[e] * ls;
            float a = (gated > 0.f) ? 1.f : 0.f;
            act[e] = a; suma += a;
        }
        if (suma == 0.f) {
            int k = min_experts_p ? *min_experts_p : 2;
            if (k <= 0 || k > E) {
                float f = __int_as_float(k);
                int k2 = (int)f;
                k = (k2 > 0 && k2 <= E) ? k2 : 2;
            }
            bool chosen[MAX_E];
            for (int e = 0; e < E; e++) chosen[e] = false;
            for (int j = 0; j < k; j++) {
                int best = -1; float bv = -1e30f;
                for (int e = 0; e < E; e++)
                    if (!chosen[e] && logits[e] > bv) { bv = logits[e]; best = e; }
                if (best >= 0) { chosen[best] = true; act[best] = 1.f; suma += 1.f; }
            }
        }
        float num = fmaxf(suma, 1.f);
        for (int e = 0; e < E; e++) {
            out_logits[(size_t)n * E + e] = logits[e];
            out_act[(size_t)n * E + e] = act[e];
            g_scale[(size_t)n * E + e] = act[e] / num;
        }
    }
}

// ---------------- fp32 -> bf16 hi/lo split of H ----------------
__global__ void split_h_kernel(const float* __restrict__ in, int total4) {
    int i4 = blockIdx.x * blockDim.x + threadIdx.x;
    if (i4 >= total4) return;
    float4 v = ((const float4*)in)[i4];
    __nv_bfloat16 h0 = __float2bfloat16(v.x), h1 = __float2bfloat16(v.y);
    __nv_bfloat16 h2 = __float2bfloat16(v.z), h3 = __float2bfloat16(v.w);
    __nv_bfloat16 l0 = __float2bfloat16(v.x - __bfloat162float(h0));
    __nv_bfloat16 l1 = __float2bfloat16(v.y - __bfloat162float(h1));
    __nv_bfloat16 l2 = __float2bfloat16(v.z - __bfloat162float(h2));
    __nv_bfloat16 l3 = __float2bfloat16(v.w - __bfloat162float(h3));
    uint2 hp, lp;
    hp.x = (uint32_t)__bfloat16_as_ushort(h0) | ((uint32_t)__bfloat16_as_ushort(h1) << 16);
    hp.y = (uint32_t)__bfloat16_as_ushort(h2) | ((uint32_t)__bfloat16_as_ushort(h3) << 16);
    lp.x = (uint32_t)__bfloat16_as_ushort(l0) | ((uint32_t)__bfloat16_as_ushort(l1) << 16);
    lp.y = (uint32_t)__bfloat16_as_ushort(l2) | ((uint32_t)__bfloat16_as_ushort(l3) << 16);
    ((uint2*)g_h_hi)[i4] = hp;
    ((uint2*)g_h_lo)[i4] = lp;
}

// ---------------- transpose + split weights ----------------
// W==0: w1 [E][C][I] -> g_w1t [E][I][C];  W==1: w2 [E][I][C'] -> g_w2t [E][C'][I]
template <int W>
__global__ void tsplit_kernel(const float* __restrict__ in, int R, int Cc) {
    __shared__ float t[32][33];
    int e = blockIdx.z;
    const float* src = in + (size_t)e * R * Cc;
    __nv_bfloat16* ohi = (W == 0 ? g_w1t_hi : g_w2t_hi) + (size_t)e * R * Cc;
    __nv_bfloat16* olo = (W == 0 ? g_w1t_lo : g_w2t_lo) + (size_t)e * R * Cc;
    int cbase = blockIdx.x * 32, rbase = blockIdx.y * 32;
    #pragma unroll
    for (int i = 0; i < 4; i++) {
        int r = rbase + threadIdx.y + i * 8;
        t[threadIdx.y + i * 8][threadIdx.x] = src[(size_t)r * Cc + cbase + threadIdx.x];
    }
    __syncthreads();
    #pragma unroll
    for (int i = 0; i < 4; i++) {
        int n = cbase + threadIdx.y + i * 8;
        int k = rbase + threadIdx.x;
        float v = t[threadIdx.x][threadIdx.y + i * 8];
        __nv_bfloat16 hi = __float2bfloat16(v);
        __nv_bfloat16 lo = __float2bfloat16(v - __bfloat162float(hi));
        ohi[(size_t)n * R + k] = hi;
        olo[(size_t)n * R + k] = lo;
    }
}

// ---------------- HMMA bf16x3 GEMM ----------------
// CTA tile 128x128, BK=32 bf16. 8 warps: warp tile 64(M) x 32(N).
// SMEM per stage: 4 matrices (Ahi, Alo, Bhi, Blo) of [128][32] bf16 padded to
// 40 elems/row (80 B) = 10240 B each -> 40960 B/stage, double-buffered.
// MODE 0: inter[e] = gelu(H @ W1t[e]^T)   A=g_h (K=C),    ncols=I
// MODE 1: part[e]  = inter[e] @ W2t[e]^T  A=g_inter[e] (K=I), ncols=C
static constexpr int SMEM_GEMM = 2 * 40960;

template <int MODE>
__global__ __launch_bounds__(256)
void mma_gemm(int K, int ncols) {
    extern __shared__ __align__(128) char smem[];
    const int tid = threadIdx.x;
    const int wid = tid >> 5, lane = tid & 31;
    const int e = blockIdx.z;
    const int m0 = blockIdx.y * 128, n0 = blockIdx.x * 128;
    const int wm = wid & 1, wn = wid >> 1;

    const __nv_bfloat16* Ah = (MODE == 0) ? g_h_hi : g_inter_hi + (size_t)e * MAX_N * MAX_I;
    const __nv_bfloat16* Al = (MODE == 0) ? g_h_lo : g_inter_lo + (size_t)e * MAX_N * MAX_I;
    const __nv_bfloat16* Bh = ((MODE == 0) ? g_w1t_hi : g_w2t_hi) + (size_t)e * ncols * K;
    const __nv_bfloat16* Bl = ((MODE == 0) ? g_w1t_lo : g_w2t_lo) + (size_t)e * ncols * K;

    const __nv_bfloat16* srcs[4] = {
        Ah + (size_t)m0 * K, Al + (size_t)m0 * K,
        Bh + (size_t)n0 * K, Bl + (size_t)n0 * K
    };

    const uint32_t sb = smem_to_u32(smem);

    auto load_stage = [&](int buf, int k0) {
        uint32_t base = sb + (uint32_t)buf * 40960u;
        #pragma unroll
        for (int m = 0; m < 4; m++) {
            #pragma unroll
            for (int i = 0; i < 2; i++) {
                int q = tid + i * 256;
                int row = q >> 2, c16 = q & 3;
                const __nv_bfloat16* g = srcs[m] + (size_t)row * K + k0 + c16 * 8;
                uint32_t s = base + (uint32_t)m * 10240u + (uint32_t)row * 80u + (uint32_t)c16 * 16u;
                CP_ASYNC16(s, g);
            }
        }
        CP_COMMIT();
    };

    const int NC = K >> 5;
    load_stage(0, 0);
    load_stage(1, 32);

    float acc[4][4][4];
    #pragma unroll
    for (int a = 0; a < 4; a++)
        #pragma unroll
        for (int b = 0; b < 4; b++)
            #pragma unroll
            for (int d = 0; d < 4; d++) acc[a][b][d] = 0.f;

    for (int c = 0; c < NC; c++) {
        if (c == NC - 1) { CP_WAIT0(); } else { CP_WAIT1(); }
        __syncthreads();
        uint32_t base = sb + (uint32_t)(c & 1) * 40960u;

        #pragma unroll
        for (int ks = 0; ks < 2; ks++) {
            uint32_t Afh[4][4], Afl[4][4], Bfh[4][2], Bfl[4][2];
            // A fragments: lanes 0-15 rows 0-15 (col ks*16), lanes 16-31 same rows col +8
            int arow = wm * 64 + (lane & 15);
            int acolb = (ks * 16 + (lane >> 4) * 8) * 2;
            #pragma unroll
            for (int mt = 0; mt < 4; mt++) {
                uint32_t ad = base + (uint32_t)(arow + mt * 16) * 80u + (uint32_t)acolb;
                LDSM4(Afh[mt], ad);
                LDSM4(Afl[mt], ad + 10240u);
            }
            // B fragments: lanes 0-7 -> rows n, k0..7; lanes 8-15 -> rows n, k8..15
            int brow = wn * 32 + (lane & 7);
            int bkb = (ks * 16 + ((lane >> 3) & 1) * 8) * 2;
            #pragma unroll
            for (int nt = 0; nt < 4; nt++) {
                uint32_t bd = base + 20480u + (uint32_t)(brow + nt * 8) * 80u + (uint32_t)bkb;
                LDSM2(Bfh[nt], bd);
                LDSM2(Bfl[nt], bd + 10240u);
            }
            // pass 1: hi*hi
            #pragma unroll
            for (int mt = 0; mt < 4; mt++)
                #pragma unroll
                for (int nt = 0; nt < 4; nt++)
                    MMA16816(acc[mt][nt], Afh[mt], Bfh[nt]);
            // pass 2: hi*lo
            #pragma unroll
            for (int mt = 0; mt < 4; mt++)
                #pragma unroll
                for (int nt = 0; nt < 4; nt++)
                    MMA16816(acc[mt][nt], Afh[mt], Bfl[nt]);
            // pass 3: lo*hi
            #pragma unroll
            for (int mt = 0; mt < 4; mt++)
                #pragma unroll
                for (int nt = 0; nt < 4; nt++)
                    MMA16816(acc[mt][nt], Afl[mt], Bfh[nt]);
        }
        __syncthreads();
        if (c + 2 < NC) load_stage(c & 1, (c + 2) * 32);
    }

    // ---------------- epilogue ----------------
    const int gq = lane >> 2, t2 = (lane & 3) * 2;
    if (MODE == 0) {
        __nv_bfloat16* oh = g_inter_hi + (size_t)e * MAX_N * MAX_I;
        __nv_bfloat16* ol = g_inter_lo + (size_t)e * MAX_N * MAX_I;
        #pragma unroll
        for (int mt = 0; mt < 4; mt++) {
            #pragma unroll
            for (int nt = 0; nt < 4; nt++) {
                int col = n0 + wn * 32 + nt * 8 + t2;
                #pragma unroll
                for (int hf = 0; hf < 2; hf++) {
                    int row = m0 + wm * 64 + mt * 16 + gq + hf * 8;
                    float x0 = acc[mt][nt][2 * hf];
                    float x1 = acc[mt][nt][2 * hf + 1];
                    float g0 = 0.5f * x0 * (1.f + erff(x0 * 0.70710678118654752f));
                    float g1 = 0.5f * x1 * (1.f + erff(x1 * 0.70710678118654752f));
                    __nv_bfloat16 h0 = __float2bfloat16(g0);
                    __nv_bfloat16 h1 = __float2bfloat16(g1);
                    __nv_bfloat16 l0 = __float2bfloat16(g0 - __bfloat162float(h0));
                    __nv_bfloat16 l1 = __float2bfloat16(g1 - __bfloat162float(h1));
                    uint32_t hp = (uint32_t)__bfloat16_as_ushort(h0) |
                                  ((uint32_t)__bfloat16_as_ushort(h1) << 16);
                    uint32_t lp = (uint32_t)__bfloat16_as_ushort(l0) |
                                  ((uint32_t)__bfloat16_as_ushort(l1) << 16);
                    *(uint32_t*)(oh + (size_t)row * ncols + col) = hp;
                    *(uint32_t*)(ol + (size_t)row * ncols + col) = lp;
                }
            }
        }
    } else {
        float* op = g_part + (size_t)e * MAX_N * MAX_C;
        #pragma unroll
        for (int mt = 0; mt < 4; mt++) {
            #pragma unroll
            for (int nt = 0; nt < 4; nt++) {
                int col = n0 + wn * 32 + nt * 8 + t2;
                #pragma unroll
                for (int hf = 0; hf < 2; hf++) {
                    int row = m0 + wm * 64 + mt * 16 + gq + hf * 8;
                    float2 v = make_float2(acc[mt][nt][2 * hf], acc[mt][nt][2 * hf + 1]);
                    *(float2*)(op + (size_t)row * ncols + col) = v;
                }
            }
        }
    }
}

// ---------------- reduce: final = sum_e scale[n][e] * part[e][n][:] ----------------
__global__ void reduce_kernel(float* __restrict__ out, int N, int C, int E) {
    int i = blockIdx.x * blockDim.x + threadIdx.x;
    int per_row = C / 4;
    if (i >= N * per_row) return;
    int n = i / per_row, c4 = i % per_row;
    float4 acc = make_float4(0.f, 0.f, 0.f, 0.f);
    const float* sr = g_scale + (size_t)n * E;
    for (int e = 0; e < E; e++) {
        float s = sr[e];
        if (s != 0.f) {
            float4 p = ((const float4*)(g_part + (size_t)e * MAX_N * MAX_C + (size_t)n * C))[c4];
            acc.x += s * p.x; acc.y += s * p.y; acc.z += s * p.z; acc.w += s * p.w;
        }
    }
    ((float4*)(out + (size_t)n * C))[c4] = acc;
}

// ---------------- launch ----------------
extern "C" void kernel_launch(void* const* d_in, const int* in_sizes, int n_in,
                              void* d_out, int out_size) {
    const float* h     = (const float*)d_in[0];
    const float* sim   = (const float*)d_in[1];
    const float* gates = (const float*)d_in[2];
    const float* temp  = (const float*)d_in[3];
    const float* mask  = (const float*)d_in[4];
    const float* w1    = (const float*)d_in[5];
    const float* w2    = (const float*)d_in[6];
    const int*   mi    = (const int*)d_in[7];

    const int E = in_sizes[2];
    const int C = in_sizes[1] / E;
    const int I = in_sizes[5] / (E * C);
    const int N = in_sizes[0] / C;

    float* out_final  = (float*)d_out;
    float* out_logits = out_final + (size_t)N * C;
    float* out_act    = out_logits + (size_t)N * E;

    static int smem_set = 0;
    if (!smem_set) {
        cudaFuncSetAttribute(mma_gemm<0>, cudaFuncAttributeMaxDynamicSharedMemorySize, SMEM_GEMM);
        cudaFuncSetAttribute(mma_gemm<1>, cudaFuncAttributeMaxDynamicSharedMemorySize, SMEM_GEMM);
        smem_set = 1;
    }

    prec_kernel<<<1, 256>>>(sim, temp, C, E);
    gating_kernel<<<N, 128>>>(h, sim, gates, mask, mi, out_logits, out_act, C, E);

    int total4 = (N * C) / 4;
    split_h_kernel<<<(total4 + 255) / 256, 256>>>(h, total4);
    tsplit_kernel<0><<<dim3(I / 32, C / 32, E), dim3(32, 8)>>>(w1, C, I);
    tsplit_kernel<1><<<dim3(C / 32, I / 32, E), dim3(32, 8)>>>(w2, I, C);

    // phase 1: inter[e] = gelu(H @ W1t[e]^T), all experts concurrent
    mma_gemm<0><<<dim3(I / 128, N / 128, E), 256, SMEM_GEMM>>>(C, I);
    // phase 2: part[e] = inter[e] @ W2t[e]^T, all experts concurrent
    mma_gemm<1><<<dim3(C / 128, N / 128, E), 256, SMEM_GEMM>>>(I, C);
    // reduce
    int rthreads = N * (C / 4);
    reduce_kernel<<<(rthreads + 255) / 256, 256>>>(out_final, N, C, E);
}

// round 4
// speedup vs baseline: 4.8613x; 1.7683x over previous
#include <cuda_runtime.h>
#include <cuda_bf16.h>
#include <math.h>
#include <stdint.h>

// Fixed shapes: N=4096 tokens, C=1024, I=2048, E=8.
#define MAX_N 4096
#define MAX_C 1024
#define MAX_I 2048
#define MAX_E 8

// ---------------- device scratch ----------------
__device__ __align__(256) __nv_bfloat16 g_h_hi[(size_t)MAX_N * MAX_C];
__device__ __align__(256) __nv_bfloat16 g_h_lo[(size_t)MAX_N * MAX_C];
__device__ __align__(256) __nv_bfloat16 g_inter_hi[(size_t)MAX_E * MAX_N * MAX_I]; // compact rows
__device__ __align__(256) __nv_bfloat16 g_inter_lo[(size_t)MAX_E * MAX_N * MAX_I];
__device__ __align__(256) __nv_bfloat16 g_w1t_hi[(size_t)MAX_E * MAX_I * MAX_C]; // [E][I][C]
__device__ __align__(256) __nv_bfloat16 g_w1t_lo[(size_t)MAX_E * MAX_I * MAX_C];
__device__ __align__(256) __nv_bfloat16 g_w2t_hi[(size_t)MAX_E * MAX_C * MAX_I]; // [E][C][I]
__device__ __align__(256) __nv_bfloat16 g_w2t_lo[(size_t)MAX_E * MAX_C * MAX_I];
__device__ __align__(256) float g_part[(size_t)MAX_E * MAX_N * MAX_C];           // compact rows
__device__ __align__(256) float g_scale[(size_t)MAX_N * MAX_E];
__device__ __align__(256) int   g_tok[(size_t)MAX_E * MAX_N];
__device__ __align__(256) int   g_pos[(size_t)MAX_N * MAX_E];
__device__ int   g_cnt[MAX_E];
__device__ float g_prec[MAX_E + 1];

#define L2_EPS 1e-12f

// ---------------- PTX helpers (baseline sm_80+ features only) ----------------
__device__ __forceinline__ uint32_t smem_to_u32(const void* p) {
    uint32_t a;
    asm("{ .reg .u64 t; cvta.to.shared.u64 t, %1; cvt.u32.u64 %0, t; }" : "=r"(a) : "l"(p));
    return a;
}
#define CP_ASYNC16(s, g) \
    asm volatile("cp.async.cg.shared.global [%0], [%1], 16;" :: "r"(s), "l"(g))
#define CP_COMMIT() asm volatile("cp.async.commit_group;" ::: "memory")
#define CP_WAIT0()  asm volatile("cp.async.wait_group 0;" ::: "memory")
#define CP_WAIT1()  asm volatile("cp.async.wait_group 1;" ::: "memory")
#define LDSM4(R, addr) \
    asm volatile("ldmatrix.sync.aligned.m8n8.x4.shared.b16 {%0,%1,%2,%3}, [%4];" \
        : "=r"((R)[0]), "=r"((R)[1]), "=r"((R)[2]), "=r"((R)[3]) : "r"(addr))
#define LDSM2(R, addr) \
    asm volatile("ldmatrix.sync.aligned.m8n8.x2.shared.b16 {%0,%1}, [%2];" \
        : "=r"((R)[0]), "=r"((R)[1]) : "r"(addr))
#define MMA16816(Cc, A, B) \
    asm volatile("mma.sync.aligned.m16n8k16.row.col.f32.bf16.bf16.f32 " \
        "{%0,%1,%2,%3}, {%4,%5,%6,%7}, {%8,%9}, {%0,%1,%2,%3};" \
        : "+f"((Cc)[0]), "+f"((Cc)[1]), "+f"((Cc)[2]), "+f"((Cc)[3]) \
        : "r"((A)[0]), "r"((A)[1]), "r"((A)[2]), "r"((A)[3]), "r"((B)[0]), "r"((B)[1]))

// ---------------- prep: sim col norms + logit scale + zero counters ----------------
__global__ void prec_kernel(const float* __restrict__ sim, const float* __restrict__ temp,
                            int C, int E) {
    int w = threadIdx.x >> 5, lane = threadIdx.x & 31;
    if (w < E) {
        float s = 0.f;
        for (int c = lane; c < C; c += 32) { float v = sim[(size_t)c * E + w]; s += v * v; }
        #pragma unroll
        for (int o = 16; o > 0; o >>= 1) s += __shfl_xor_sync(0xffffffffu, s, o);
        if (lane == 0) g_prec[w] = 1.f / fmaxf(sqrtf(s), L2_EPS);
    }
    if (threadIdx.x == 0) g_prec[MAX_E] = 1.f / (1.f + expf(-temp[0]));
    if (threadIdx.x < MAX_E) g_cnt[threadIdx.x] = 0;
}

// ---------------- gating ----------------
__global__ void gating_kernel(const float* __restrict__ h, const float* __restrict__ sim,
                              const float* __restrict__ gates, const float* __restrict__ mask,
                              const int* __restrict__ min_experts_p,
                              float* __restrict__ out_logits, float* __restrict__ out_act,
                              int C, int E) {
    const int n = blockIdx.x, tid = threadIdx.x;
    float hh = 0.f;
    float dot[MAX_E];
    #pragma unroll
    for (int e = 0; e < MAX_E; e++) dot[e] = 0.f;
    const float* hrow = h + (size_t)n * C;
    for (int c = tid; c < C; c += 128) {
        float v = hrow[c];
        hh += v * v;
        const float* srow = sim + (size_t)c * E;
        #pragma unroll
        for (int e = 0; e < MAX_E; e++) if (e < E) dot[e] += v * srow[e];
    }
    __shared__ float sd[(MAX_E + 1) * 128];
    sd[tid] = hh;
    #pragma unroll
    for (int e = 0; e < MAX_E; e++) if (e < E) sd[(e + 1) * 128 + tid] = dot[e];
    __syncthreads();
    for (int s = 64; s > 0; s >>= 1) {
        if (tid < s)
            for (int r = 0; r <= E; r++) sd[r * 128 + tid] += sd[r * 128 + tid + s];
        __syncthreads();
    }
    if (tid == 0) {
        float inv_h = 1.f / fmaxf(sqrtf(sd[0]), L2_EPS);
        float ls = g_prec[MAX_E];
        float logits[MAX_E], act[MAX_E];
        float suma = 0.f;
        for (int e = 0; e < E; e++) {
            float lg = sd[(e + 1) * 128] * inv_h * g_prec[e];
            lg *= mask[e];
            logits[e] = lg;
            float gated = lg - gates[e] * ls;
            float a = (gated > 0.f) ? 1.f : 0.f;
            act[e] = a; suma += a;
        }
        if (suma == 0.f) {
            int k = min_experts_p ? *min_experts_p : 2;
            if (k <= 0 || k > E) {
                float f = __int_as_float(k);
                int k2 = (int)f;
                k = (k2 > 0 && k2 <= E) ? k2 : 2;
            }
            bool chosen[MAX_E];
            for (int e = 0; e < E; e++) chosen[e] = false;
            for (int j = 0; j < k; j++) {
                int best = -1; float bv = -1e30f;
                for (int e = 0; e < E; e++)
                    if (!chosen[e] && logits[e] > bv) { bv = logits[e]; best = e; }
                if (best >= 0) { chosen[best] = true; act[best] = 1.f; suma += 1.f; }
            }
        }
        float num = fmaxf(suma, 1.f);
        for (int e = 0; e < E; e++) {
            out_logits[(size_t)n * E + e] = logits[e];
            out_act[(size_t)n * E + e] = act[e];
            g_scale[(size_t)n * E + e] = act[e] / num;
        }
    }
}

// ---------------- compaction: per-expert active-token lists ----------------
__global__ void compact_kernel(int N, int E) {
    int n = blockIdx.x * blockDim.x + threadIdx.x;
    if (n >= N) return;
    for (int e = 0; e < E; e++) {
        if (g_scale[(size_t)n * E + e] != 0.f) {
            int slot = atomicAdd(&g_cnt[e], 1);
            g_tok[(size_t)e * MAX_N + slot] = n;
            g_pos[(size_t)n * E + e] = slot;
        }
    }
}

// ---------------- fp32 -> bf16 hi/lo split of H ----------------
__global__ void split_h_kernel(const float* __restrict__ in, int total4) {
    int i4 = blockIdx.x * blockDim.x + threadIdx.x;
    if (i4 >= total4) return;
    float4 v = ((const float4*)in)[i4];
    __nv_bfloat16 h0 = __float2bfloat16(v.x), h1 = __float2bfloat16(v.y);
    __nv_bfloat16 h2 = __float2bfloat16(v.z), h3 = __float2bfloat16(v.w);
    __nv_bfloat16 l0 = __float2bfloat16(v.x - __bfloat162float(h0));
    __nv_bfloat16 l1 = __float2bfloat16(v.y - __bfloat162float(h1));
    __nv_bfloat16 l2 = __float2bfloat16(v.z - __bfloat162float(h2));
    __nv_bfloat16 l3 = __float2bfloat16(v.w - __bfloat162float(h3));
    uint2 hp, lp;
    hp.x = (uint32_t)__bfloat16_as_ushort(h0) | ((uint32_t)__bfloat16_as_ushort(h1) << 16);
    hp.y = (uint32_t)__bfloat16_as_ushort(h2) | ((uint32_t)__bfloat16_as_ushort(h3) << 16);
    lp.x = (uint32_t)__bfloat16_as_ushort(l0) | ((uint32_t)__bfloat16_as_ushort(l1) << 16);
    lp.y = (uint32_t)__bfloat16_as_ushort(l2) | ((uint32_t)__bfloat16_as_ushort(l3) << 16);
    ((uint2*)g_h_hi)[i4] = hp;
    ((uint2*)g_h_lo)[i4] = lp;
}

// ---------------- transpose + split weights ----------------
template <int W>
__global__ void tsplit_kernel(const float* __restrict__ in, int R, int Cc) {
    __shared__ float t[32][33];
    int e = blockIdx.z;
    const float* src = in + (size_t)e * R * Cc;
    __nv_bfloat16* ohi = (W == 0 ? g_w1t_hi : g_w2t_hi) + (size_t)e * R * Cc;
    __nv_bfloat16* olo = (W == 0 ? g_w1t_lo : g_w2t_lo) + (size_t)e * R * Cc;
    int cbase = blockIdx.x * 32, rbase = blockIdx.y * 32;
    #pragma unroll
    for (int i = 0; i < 4; i++) {
        int r = rbase + threadIdx.y + i * 8;
        t[threadIdx.y + i * 8][threadIdx.x] = src[(size_t)r * Cc + cbase + threadIdx.x];
    }
    __syncthreads();
    #pragma unroll
    for (int i = 0; i < 4; i++) {
        int n = cbase + threadIdx.y + i * 8;
        int k = rbase + threadIdx.x;
        float v = t[threadIdx.x][threadIdx.y + i * 8];
        __nv_bfloat16 hi = __float2bfloat16(v);
        __nv_bfloat16 lo = __float2bfloat16(v - __bfloat162float(hi));
        ohi[(size_t)n * R + k] = hi;
        olo[(size_t)n * R + k] = lo;
    }
}

// ---------------- HMMA bf16x3 GEMM over compacted tokens ----------------
// MODE 0: inter[e][slot] = gelu(H[tok[e][slot]] @ W1t[e]^T)  K=C, ncols=I (A gathered)
// MODE 1: part[e][slot]  = inter[e][slot] @ W2t[e]^T         K=I, ncols=C (A compact)
static constexpr int SMEM_GEMM = 2 * 40960;

template <int MODE>
__global__ __launch_bounds__(256)
void mma_gemm(int K, int ncols) {
    extern __shared__ __align__(128) char smem[];
    const int tid = threadIdx.x;
    const int wid = tid >> 5, lane = tid & 31;
    const int e = blockIdx.z;
    const int m0 = blockIdx.y * 128, n0 = blockIdx.x * 128;
    const int wm = wid & 1, wn = wid >> 1;

    const int cnt = g_cnt[e];
    if (m0 >= cnt) return;

    const __nv_bfloat16* Ah = (MODE == 0) ? g_h_hi : g_inter_hi + (size_t)e * MAX_N * MAX_I;
    const __nv_bfloat16* Al = (MODE == 0) ? g_h_lo : g_inter_lo + (size_t)e * MAX_N * MAX_I;
    const __nv_bfloat16* Bh = ((MODE == 0) ? g_w1t_hi : g_w2t_hi) + (size_t)e * ncols * K + (size_t)n0 * K;
    const __nv_bfloat16* Bl = ((MODE == 0) ? g_w1t_lo : g_w2t_lo) + (size_t)e * ncols * K + (size_t)n0 * K;

    // Per-thread A row indices for the two copy rows it owns (r0 and r0+64).
    const int r0 = tid >> 2;
    int ga0, ga1;
    if (MODE == 0) {
        const int* tk = g_tok + (size_t)e * MAX_N;
        ga0 = tk[min(m0 + r0, cnt - 1)];
        ga1 = tk[min(m0 + r0 + 64, cnt - 1)];
    } else {
        ga0 = min(m0 + r0, cnt - 1);
        ga1 = min(m0 + r0 + 64, cnt - 1);
    }
    const int c16 = (tid & 3);

    const uint32_t sb = smem_to_u32(smem);

    auto load_stage = [&](int buf, int k0) {
        uint32_t base = sb + (uint32_t)buf * 40960u;
        #pragma unroll
        for (int i = 0; i < 2; i++) {
            int row = (i == 0) ? r0 : r0 + 64;
            int arow = (i == 0) ? ga0 : ga1;
            uint32_t soff = (uint32_t)row * 80u + (uint32_t)c16 * 16u;
            CP_ASYNC16(base + soff,           Ah + (size_t)arow * K + k0 + c16 * 8);
            CP_ASYNC16(base + 10240u + soff,  Al + (size_t)arow * K + k0 + c16 * 8);
            CP_ASYNC16(base + 20480u + soff,  Bh + (size_t)row * K + k0 + c16 * 8);
            CP_ASYNC16(base + 30720u + soff,  Bl + (size_t)row * K + k0 + c16 * 8);
        }
        CP_COMMIT();
    };

    const int NC = K >> 5;
    load_stage(0, 0);
    load_stage(1, 32);

    float acc[4][4][4];
    #pragma unroll
    for (int a = 0; a < 4; a++)
        #pragma unroll
        for (int b = 0; b < 4; b++)
            #pragma unroll
            for (int d = 0; d < 4; d++) acc[a][b][d] = 0.f;

    for (int c = 0; c < NC; c++) {
        if (c == NC - 1) { CP_WAIT0(); } else { CP_WAIT1(); }
        __syncthreads();
        uint32_t base = sb + (uint32_t)(c & 1) * 40960u;

        #pragma unroll
        for (int ks = 0; ks < 2; ks++) {
            uint32_t Afh[4][4], Afl[4][4], Bfh[4][2], Bfl[4][2];
            int arow = wm * 64 + (lane & 15);
            int acolb = (ks * 16 + (lane >> 4) * 8) * 2;
            #pragma unroll
            for (int mt = 0; mt < 4; mt++) {
                uint32_t ad = base + (uint32_t)(arow + mt * 16) * 80u + (uint32_t)acolb;
                LDSM4(Afh[mt], ad);
                LDSM4(Afl[mt], ad + 10240u);
            }
            int brow = wn * 32 + (lane & 7);
            int bkb = (ks * 16 + ((lane >> 3) & 1) * 8) * 2;
            #pragma unroll
            for (int nt = 0; nt < 4; nt++) {
                uint32_t bd = base + 20480u + (uint32_t)(brow + nt * 8) * 80u + (uint32_t)bkb;
                LDSM2(Bfh[nt], bd);
                LDSM2(Bfl[nt], bd + 10240u);
            }
            #pragma unroll
            for (int mt = 0; mt < 4; mt++)
                #pragma unroll
                for (int nt = 0; nt < 4; nt++)
                    MMA16816(acc[mt][nt], Afh[mt], Bfh[nt]);
            #pragma unroll
            for (int mt = 0; mt < 4; mt++)
                #pragma unroll
                for (int nt = 0; nt < 4; nt++)
                    MMA16816(acc[mt][nt], Afh[mt], Bfl[nt]);
            #pragma unroll
            for (int mt = 0; mt < 4; mt++)
                #pragma unroll
                for (int nt = 0; nt < 4; nt++)
                    MMA16816(acc[mt][nt], Afl[mt], Bfh[nt]);
        }
        __syncthreads();
        if (c + 2 < NC) load_stage(c & 1, (c + 2) * 32);
    }

    // ---------------- epilogue (compact rows, guarded by cnt) ----------------
    const int gq = lane >> 2, t2 = (lane & 3) * 2;
    if (MODE == 0) {
        __nv_bfloat16* oh = g_inter_hi + (size_t)e * MAX_N * MAX_I;
        __nv_bfloat16* ol = g_inter_lo + (size_t)e * MAX_N * MAX_I;
        #pragma unroll
        for (int mt = 0; mt < 4; mt++) {
            #pragma unroll
            for (int nt = 0; nt < 4; nt++) {
                int col = n0 + wn * 32 + nt * 8 + t2;
                #pragma unroll
                for (int hf = 0; hf < 2; hf++) {
                    int row = m0 + wm * 64 + mt * 16 + gq + hf * 8;
                    if (row >= cnt) continue;
                    float x0 = acc[mt][nt][2 * hf];
                    float x1 = acc[mt][nt][2 * hf + 1];
                    float g0 = 0.5f * x0 * (1.f + erff(x0 * 0.70710678118654752f));
                    float g1 = 0.5f * x1 * (1.f + erff(x1 * 0.70710678118654752f));
                    __nv_bfloat16 h0 = __float2bfloat16(g0);
                    __nv_bfloat16 h1 = __float2bfloat16(g1);
                    __nv_bfloat16 l0 = __float2bfloat16(g0 - __bfloat162float(h0));
                    __nv_bfloat16 l1 = __float2bfloat16(g1 - __bfloat162float(h1));
                    uint32_t hp = (uint32_t)__bfloat16_as_ushort(h0) |
                                  ((uint32_t)__bfloat16_as_ushort(h1) << 16);
                    uint32_t lp = (uint32_t)__bfloat16_as_ushort(l0) |
                                  ((uint32_t)__bfloat16_as_ushort(l1) << 16);
                    *(uint32_t*)(oh + (size_t)row * ncols + col) = hp;
                    *(uint32_t*)(ol + (size_t)row * ncols + col) = lp;
                }
            }
        }
    } else {
        float* op = g_part + (size_t)e * MAX_N * MAX_C;
        #pragma unroll
        for (int mt = 0; mt < 4; mt++) {
            #pragma unroll
            for (int nt = 0; nt < 4; nt++) {
                int col = n0 + wn * 32 + nt * 8 + t2;
                #pragma unroll
                for (int hf = 0; hf < 2; hf++) {
                    int row = m0 + wm * 64 + mt * 16 + gq + hf * 8;
                    if (row >= cnt) continue;
                    float2 v = make_float2(acc[mt][nt][2 * hf], acc[mt][nt][2 * hf + 1]);
                    *(float2*)(op + (size_t)row * ncols + col) = v;
                }
            }
        }
    }
}

// ---------------- reduce: final[n] = sum_e scale[n][e] * part[e][pos[n][e]] ----------------
__global__ void reduce_kernel(float* __restrict__ out, int N, int C, int E) {
    int i = blockIdx.x * blockDim.x + threadIdx.x;
    int per_row = C / 4;
    if (i >= N * per_row) return;
    int n = i / per_row, c4 = i % per_row;
    float4 acc = make_float4(0.f, 0.f, 0.f, 0.f);
    const float* sr = g_scale + (size_t)n * E;
    const int* pr = g_pos + (size_t)n * E;
    for (int e = 0; e < E; e++) {
        float s = sr[e];
        if (s != 0.f) {
            int p = pr[e];
            float4 v = ((const float4*)(g_part + (size_t)e * MAX_N * MAX_C + (size_t)p * C))[c4];
            acc.x += s * v.x; acc.y += s * v.y; acc.z += s * v.z; acc.w += s * v.w;
        }
    }
    ((float4*)(out + (size_t)n * C))[c4] = acc;
}

// ---------------- launch ----------------
extern "C" void kernel_launch(void* const* d_in, const int* in_sizes, int n_in,
                              void* d_out, int out_size) {
    const float* h     = (const float*)d_in[0];
    const float* sim   = (const float*)d_in[1];
    const float* gates = (const float*)d_in[2];
    const float* temp  = (const float*)d_in[3];
    const float* mask  = (const float*)d_in[4];
    const float* w1    = (const float*)d_in[5];
    const float* w2    = (const float*)d_in[6];
    const int*   mi    = (const int*)d_in[7];

    const int E = in_sizes[2];
    const int C = in_sizes[1] / E;
    const int I = in_sizes[5] / (E * C);
    const int N = in_sizes[0] / C;

    float* out_final  = (float*)d_out;
    float* out_logits = out_final + (size_t)N * C;
    float* out_act    = out_logits + (size_t)N * E;

    cudaFuncSetAttribute(mma_gemm<0>, cudaFuncAttributeMaxDynamicSharedMemorySize, SMEM_GEMM);
    cudaFuncSetAttribute(mma_gemm<1>, cudaFuncAttributeMaxDynamicSharedMemorySize, SMEM_GEMM);

    prec_kernel<<<1, 256>>>(sim, temp, C, E);
    gating_kernel<<<N, 128>>>(h, sim, gates, mask, mi, out_logits, out_act, C, E);
    compact_kernel<<<(N + 255) / 256, 256>>>(N, E);

    int total4 = (N * C) / 4;
    split_h_kernel<<<(total4 + 255) / 256, 256>>>(h, total4);
    tsplit_kernel<0><<<dim3(I / 32, C / 32, E), dim3(32, 8)>>>(w1, C, I);
    tsplit_kernel<1><<<dim3(C / 32, I / 32, E), dim3(32, 8)>>>(w2, I, C);

    mma_gemm<0><<<dim3(I / 128, N / 128, E), 256, SMEM_GEMM>>>(C, I);
    mma_gemm<1><<<dim3(C / 128, N / 128, E), 256, SMEM_GEMM>>>(I, C);

    int rthreads = N * (C / 4);
    reduce_kernel<<<(rthreads + 255) / 256, 256>>>(out_final, N, C, E);
}